// round 9
// baseline (speedup 1.0000x reference)
#include <cuda_runtime.h>

// Bidirectional LSTM, H=39, B=512, T=2048, fp32 — two-phase.
// Phase 1 (pre_kernel): pre[dir][b][t][row] = W_ih[row,:]·x[b,t,:] + b_ih + b_hh
//   for all rows (156) — embarrassingly parallel, writes 1.31 GB scratch.
// Phase 2 (lstm_rec_kernel): serial scan does ONLY the W_hh·h part per step,
//   reading pre (2-step register prefetch). Halves both the per-step FMA work
//   and the broadcast-LDS stream that co-bound R8.
// Recurrent shape (proven in R8): 444 blocks x 160 thr, 3 resident/SM
//   (444 = 148*3; blocks 0..135 own 3 seqs, 136..443 own 2; ids 0..135 are
//   distinct mod 148 -> max 7 seqs/SM, balanced). Lane map tid = 4*j + g;
//   4-shuffle 4x4 transpose gives lane g all gates of seq g; one barrier/step.

#define H        39
#define G4       156
#define T_STEPS  2048
#define B_TOT    512
#define MAXS     3
#define THREADS  160
#define PADW     40
#define TCHUNK   128
#define NCHUNK   (T_STEPS / TCHUNK)   // 16

// 2 * 512 * 2048 * 156 floats = 1.31 GB scratch (bss, zero-init)
__device__ float g_pre[2ULL * B_TOT * T_STEPS * G4];

union F2U { float2 f; unsigned long long u; };

__device__ __forceinline__ float2 ffma2(float2 a, float2 b, float2 c) {
    F2U A, B, C, D;
    A.f = a; B.f = b; C.f = c;
    asm("fma.rn.f32x2 %0, %1, %2, %3;" : "=l"(D.u) : "l"(A.u), "l"(B.u), "l"(C.u));
    return D.f;
}

// ---------------------------------------------------------------------------
// Phase 1: input projection. grid = 2 * 512 * 16 = 16384 blocks x 160 thr.
// bx = d*8192 + b*16 + chunk. Each block: one (dir, b), 128 timesteps.
// ---------------------------------------------------------------------------
__global__ __launch_bounds__(THREADS) void pre_kernel(
    const float* __restrict__ x,
    const float* __restrict__ Wih_f, const float* __restrict__ bih_f,
    const float* __restrict__ bhh_f,
    const float* __restrict__ Wih_b, const float* __restrict__ bih_b,
    const float* __restrict__ bhh_b)
{
    __shared__ __align__(16) float sxt[TCHUNK][PADW];

    const int tid   = threadIdx.x;
    const int bx    = blockIdx.x;
    const int chunk = bx & (NCHUNK - 1);
    const int bb    = (bx >> 4) & (B_TOT - 1);
    const int d     = bx >> 13;

    const float* Wih = d ? Wih_b : Wih_f;
    const float* bih = d ? bih_b : bih_f;
    const float* bhh = d ? bhh_b : bhh_f;

    // stage x tile [128 x 39] -> smem padded to 40
    const float* xb = x + ((size_t)bb * T_STEPS + (size_t)chunk * TCHUNK) * H;
    for (int idx = tid; idx < TCHUNK * H; idx += THREADS) {
        const int t = idx / H;
        const int k = idx - t * H;
        sxt[t][k] = xb[idx];
    }
    for (int t = tid; t < TCHUNK; t += THREADS) sxt[t][H] = 0.0f;  // pad

    // weight row in registers (padded)
    const int row = (tid < G4) ? tid : (G4 - 1);
    float2 w2[20];
    #pragma unroll
    for (int k = 0; k < 20; k++) {
        const int i0 = 2 * k, i1 = i0 + 1;
        const float a0 = Wih[row * H + i0];
        const float a1 = (i1 < H) ? Wih[row * H + i1] : 0.0f;
        w2[k] = make_float2(a0, a1);
    }
    const float bias = bih[row] + bhh[row];

    __syncthreads();

    float* po = g_pre + (((size_t)d * B_TOT + bb) * T_STEPS
                         + (size_t)chunk * TCHUNK) * G4 + row;

    #pragma unroll 2
    for (int tt = 0; tt < TCHUNK; tt++) {
        const float4* x4 = reinterpret_cast<const float4*>(sxt[tt]);
        float2 acc = make_float2(0.f, 0.f);
        #pragma unroll
        for (int k = 0; k < 10; k++) {
            const float4 xv = x4[k];
            acc = ffma2(w2[2 * k],     make_float2(xv.x, xv.y), acc);
            acc = ffma2(w2[2 * k + 1], make_float2(xv.z, xv.w), acc);
        }
        if (tid < G4) po[(size_t)tt * G4] = bias + acc.x + acc.y;
    }
}

// ---------------------------------------------------------------------------
// Phase 2: recurrence.
// ---------------------------------------------------------------------------
__global__ __launch_bounds__(THREADS, 3) void lstm_rec_kernel(
    const float* __restrict__ Whh_f, const float* __restrict__ Whh_b,
    float* __restrict__ out)
{
    __shared__ __align__(16) float sh[2][MAXS][PADW];

    const int tid = threadIdx.x;
    const int bx  = blockIdx.x;

    int nsq, start;
    if (bx < 136) { nsq = 3; start = 3 * bx; }
    else          { nsq = 2; start = 408 + 2 * (bx - 136); }
    const int dir   = (start >= B_TOT) ? 1 : 0;
    const int bbase = start - dir * B_TOT;

    const float* Whh = dir ? Whh_b : Whh_f;

    const int g  = tid & 3;            // gate 0=i 1=f 2=g 3=o; also "my" seq
    const int jj = tid >> 2;           // hidden index 0..39
    const bool jvalid = (jj < H);
    const int jc  = jvalid ? jj : (H - 1);
    const int row = g * H + jc;

    // recurrent weight row only: 20 float2 = 40 regs
    float2 whh2[20];
    #pragma unroll
    for (int k = 0; k < 20; k++) {
        const int i0 = 2 * k, i1 = i0 + 1;
        const float b0 = Whh[row * H + i0];
        const float b1 = (i1 < H) ? Whh[row * H + i1] : 0.0f;
        whh2[k] = make_float2(b0, b1);
    }

    // activation constants (g==2 -> tanh, else sigmoid)
    const float mconst = (g == 2) ?  2.0f : -1.0f;
    const float nA     = (g == 2) ?  1.0f :  0.0f;
    const float nB     = (g == 2) ? -1.0f :  1.0f;

    // zero sh (both buffers incl. pads)
    float* smf = &sh[0][0][0];
    for (int idx = tid; idx < 2 * MAXS * PADW; idx += THREADS) smf[idx] = 0.0f;

    // pre-value pointers + 2-deep prefetch registers (per seq)
    const long pstep = dir ? -(long)G4 : (long)G4;
    const float* pq[MAXS];
    float pc[MAXS], p1[MAXS];
    #pragma unroll
    for (int ss = 0; ss < MAXS; ss++) {
        const int sb = bbase + (ss < nsq ? ss : 0);
        const float* base = g_pre
            + ((size_t)dir * B_TOT + sb) * ((size_t)T_STEPS * G4)
            + (dir ? (size_t)(T_STEPS - 1) * G4 : 0) + row;
        pc[ss] = __ldg(base);
        p1[ss] = __ldg(base + pstep);
        pq[ss] = base + 2 * pstep;
    }

    const bool owner = (g < nsq) && jvalid;
    float c = 0.0f;
    const size_t oseq = (size_t)T_STEPS * 2 * H;
    float* op = out + (size_t)(bbase + (g < nsq ? g : 0)) * oseq + dir * H + jj;

    __syncthreads();

    #pragma unroll 1
    for (int t = 0; t < T_STEPS; t++) {
        const int cur = t & 1;
        const int nxt = cur ^ 1;

        // prefetch pre for t+2
        float p2[MAXS];
        #pragma unroll
        for (int ss = 0; ss < MAXS; ss++) {
            p2[ss] = (t + 2 < T_STEPS) ? __ldg(pq[ss]) : 0.0f;
            pq[ss] += pstep;
        }

        // ---- this gate row's value for each active seq (W_hh·h part only) ----
        float a[4];
        a[0] = a[1] = a[2] = a[3] = 0.0f;
        #pragma unroll
        for (int ss = 0; ss < MAXS; ss++) {
            if (ss < nsq) {
                const float4* h4 = reinterpret_cast<const float4*>(sh[cur][ss]);
                float2 aH = make_float2(0.f, 0.f);
                #pragma unroll
                for (int k = 0; k < 10; k++) {
                    const float4 hv = h4[k];
                    aH = ffma2(whh2[2 * k],     make_float2(hv.x, hv.y), aH);
                    aH = ffma2(whh2[2 * k + 1], make_float2(hv.z, hv.w), aH);
                }
                const float p = pc[ss] + (aH.x + aH.y);
                // sigmoid(p)=1/(1+e^-p); tanh(p)=(e^{2p}-1)/(e^{2p}+1)
                const float e = __expf(p * mconst);
                a[ss] = __fdividef(fmaf(e, nA, nB), e + 1.0f);
            }
        }

        // ---- 4x4 lane transpose: lane g ends with gates [i,f,g,o] of seq g ----
        const unsigned M = 0xffffffffu;
        const bool o1 = (g & 1);
        const float rA = __shfl_xor_sync(M, o1 ? a[0] : a[1], 1);
        const float rB = __shfl_xor_sync(M, o1 ? a[2] : a[3], 1);
        const float n10 = o1 ? rA   : a[0];
        const float n11 = o1 ? a[1] : rA;
        const float n12 = o1 ? rB   : a[2];
        const float n13 = o1 ? a[3] : rB;
        const bool o2 = (g & 2);
        const float rC = __shfl_xor_sync(M, o2 ? n10 : n12, 2);
        const float rD = __shfl_xor_sync(M, o2 ? n11 : n13, 2);
        const float gi = o2 ? rC  : n10;
        const float gf = o2 ? rD  : n11;
        const float gg = o2 ? n12 : rC;
        const float go = o2 ? n13 : rD;

        // ---- cell update for owned (seq=g, j) ----
        c = gf * c + gi * gg;
        const float e2 = __expf(c + c);
        const float th = 1.0f - 2.0f * __fdividef(1.0f, e2 + 1.0f);  // tanh(c)
        const float h  = go * th;

        if (owner) {
            sh[nxt][g][jj] = h;
            op[(size_t)t * (2 * H)] = h;
        }

        // rotate prefetch pipe
        #pragma unroll
        for (int ss = 0; ss < MAXS; ss++) { pc[ss] = p1[ss]; p1[ss] = p2[ss]; }

        __syncthreads();
    }
}

extern "C" void kernel_launch(void* const* d_in, const int* in_sizes, int n_in,
                              void* d_out, int out_size) {
    const float* x     = (const float*)d_in[0];
    const float* Wih_f = (const float*)d_in[1];
    const float* Whh_f = (const float*)d_in[2];
    const float* bih_f = (const float*)d_in[3];
    const float* bhh_f = (const float*)d_in[4];
    const float* Wih_b = (const float*)d_in[5];
    const float* Whh_b = (const float*)d_in[6];
    const float* bih_b = (const float*)d_in[7];
    const float* bhh_b = (const float*)d_in[8];
    float* out = (float*)d_out;

    pre_kernel<<<2 * B_TOT * NCHUNK, THREADS>>>(x, Wih_f, bih_f, bhh_f,
                                                Wih_b, bih_b, bhh_b);
    lstm_rec_kernel<<<444, THREADS>>>(Whh_f, Whh_b, out);
}

// round 10
// speedup vs baseline: 1.0756x; 1.0756x over previous
#include <cuda_runtime.h>

// Bidirectional LSTM, H=39, B=512, T=2048, fp32 — two-phase.
// Phase 1 (pre_kernel): pre[dir][b][t][row] = W_ih[row,:]·x[b,t,:] + b_ih+b_hh.
//   Register-blocked 2 rows/thread (80 weight regs) -> 10 LDS serve 40 ffma2.
//   160 threads = two 80-thread subgroups, each owning 64 timesteps of a
//   128-tt staged x tile (subgroup split at tid 80 -> warp-uniform inner loop).
// Phase 2 (lstm_rec_kernel): serial scan, W_hh·h only. 512 blocks x 2 seqs,
//   4 resident blocks/SM (launch_bounds(160,4)). Lane map tid = 4*j + g;
//   4-shuffle transpose gives lane g the gates of seq g (lanes 2,3 non-owners);
//   one barrier/step, ping-pong h buffers, unguarded 2-deep pre prefetch
//   (over-reads provably stay inside g_pre).

#define H        39
#define G4       156
#define T_STEPS  2048
#define B_TOT    512
#define THREADS  160
#define PADW     40
#define TCH      64          // timesteps per subgroup
#define TBLK     128         // timesteps staged per pre block
#define NBLKT    (T_STEPS / TBLK)   // 16

// 2 * 512 * 2048 * 156 floats = 1.31 GB scratch (bss)
__device__ float g_pre[2ULL * B_TOT * T_STEPS * G4];

union F2U { float2 f; unsigned long long u; };

__device__ __forceinline__ float2 ffma2(float2 a, float2 b, float2 c) {
    F2U A, B, C, D;
    A.f = a; B.f = b; C.f = c;
    asm("fma.rn.f32x2 %0, %1, %2, %3;" : "=l"(D.u) : "l"(A.u), "l"(B.u), "l"(C.u));
    return D.f;
}

// ---------------------------------------------------------------------------
// Phase 1. grid = 2 * 512 * 16 = 16384 blocks x 160 threads.
// bx -> (d, b, tblock). Subgroup sub = tid/80 handles tt [sub*64, sub*64+64).
// Thread r (= tid - 80*sub, r < 78) owns rows r and r+78.
// ---------------------------------------------------------------------------
__global__ __launch_bounds__(THREADS) void pre_kernel(
    const float* __restrict__ x,
    const float* __restrict__ Wih_f, const float* __restrict__ bih_f,
    const float* __restrict__ bhh_f,
    const float* __restrict__ Wih_b, const float* __restrict__ bih_b,
    const float* __restrict__ bhh_b)
{
    __shared__ __align__(16) float sxt[TBLK][PADW];

    const int tid = threadIdx.x;
    const int bx  = blockIdx.x;
    const int tb  = bx & (NBLKT - 1);
    const int bb  = (bx >> 4) & (B_TOT - 1);
    const int d   = bx >> 13;

    const float* Wih = d ? Wih_b : Wih_f;
    const float* bih = d ? bih_b : bih_f;
    const float* bhh = d ? bhh_b : bhh_f;

    // stage x tile [128 x 39] -> smem padded to 40
    const float* xb = x + ((size_t)bb * T_STEPS + (size_t)tb * TBLK) * H;
    for (int idx = tid; idx < TBLK * H; idx += THREADS) {
        const int t = idx / H;
        const int k = idx - t * H;
        sxt[t][k] = xb[idx];
    }
    for (int t = tid; t < TBLK; t += THREADS) sxt[t][H] = 0.0f;   // pad col

    const int sub = (tid >= 80) ? 1 : 0;
    const int r   = tid - 80 * sub;
    const bool valid = (r < 78);
    const int r0 = valid ? r : 77;
    const int r1 = r0 + 78;

    // two weight rows in registers (40 f32x2 = 80 regs)
    float2 w0[20], w1[20];
    #pragma unroll
    for (int k = 0; k < 20; k++) {
        const int i0 = 2 * k, i1 = i0 + 1;
        const float a0 = Wih[r0 * H + i0];
        const float a1 = (i1 < H) ? Wih[r0 * H + i1] : 0.0f;
        const float b0 = Wih[r1 * H + i0];
        const float b1 = (i1 < H) ? Wih[r1 * H + i1] : 0.0f;
        w0[k] = make_float2(a0, a1);
        w1[k] = make_float2(b0, b1);
    }
    const float bias0 = bih[r0] + bhh[r0];
    const float bias1 = bih[r1] + bhh[r1];

    __syncthreads();

    const float (*tile)[PADW] = &sxt[sub * TCH];
    float* po = g_pre + (((size_t)d * B_TOT + bb) * T_STEPS
                         + (size_t)tb * TBLK + (size_t)sub * TCH) * G4;

    #pragma unroll 2
    for (int tt = 0; tt < TCH; tt++) {
        const float4* x4 = reinterpret_cast<const float4*>(tile[tt]);
        float2 acc0 = make_float2(0.f, 0.f);
        float2 acc1 = make_float2(0.f, 0.f);
        #pragma unroll
        for (int k = 0; k < 10; k++) {
            const float4 xv = x4[k];
            const float2 lo = make_float2(xv.x, xv.y);
            const float2 hi = make_float2(xv.z, xv.w);
            acc0 = ffma2(w0[2 * k],     lo, acc0);
            acc0 = ffma2(w0[2 * k + 1], hi, acc0);
            acc1 = ffma2(w1[2 * k],     lo, acc1);
            acc1 = ffma2(w1[2 * k + 1], hi, acc1);
        }
        if (valid) {
            po[(size_t)tt * G4 + r0] = bias0 + acc0.x + acc0.y;
            po[(size_t)tt * G4 + r1] = bias1 + acc1.x + acc1.y;
        }
    }
}

// ---------------------------------------------------------------------------
// Phase 2: recurrence. 512 blocks x 160 threads, 2 seqs/block, 4 blocks/SM.
// ---------------------------------------------------------------------------
__global__ __launch_bounds__(THREADS, 4) void lstm_rec_kernel(
    const float* __restrict__ Whh_f, const float* __restrict__ Whh_b,
    float* __restrict__ out)
{
    __shared__ __align__(16) float sh[2][2][PADW];   // [pingpong][seq][j]

    const int tid = threadIdx.x;
    const int bx  = blockIdx.x;
    const int dir   = bx >> 8;
    const int bbase = (bx & 255) * 2;

    const float* Whh = dir ? Whh_b : Whh_f;

    const int g  = tid & 3;            // gate 0=i 1=f 2=g 3=o; also "my" seq
    const int jj = tid >> 2;           // hidden index 0..39
    const bool jvalid = (jj < H);
    const int jc  = jvalid ? jj : (H - 1);
    const int row = g * H + jc;

    // recurrent weight row: 20 f32x2 = 40 regs
    float2 whh2[20];
    #pragma unroll
    for (int k = 0; k < 20; k++) {
        const int i0 = 2 * k, i1 = i0 + 1;
        const float b0 = Whh[row * H + i0];
        const float b1 = (i1 < H) ? Whh[row * H + i1] : 0.0f;
        whh2[k] = make_float2(b0, b1);
    }

    // activation constants (g==2 -> tanh, else sigmoid)
    const float mconst = (g == 2) ?  2.0f : -1.0f;
    const float nA     = (g == 2) ?  1.0f :  0.0f;
    const float nB     = (g == 2) ? -1.0f :  1.0f;

    // zero h buffers (both, incl. pads)
    float* smf = &sh[0][0][0];
    for (int idx = tid; idx < 2 * 2 * PADW; idx += THREADS) smf[idx] = 0.0f;

    // pre pointers for the two seqs + 2-deep prefetch (unguarded; over-reads
    // at t in [T, T+2) resp. [-2, 0) stay inside g_pre for every (dir, b)).
    const long pstep = dir ? -(long)G4 : (long)G4;
    const float* q0 = g_pre
        + ((size_t)dir * B_TOT + bbase) * ((size_t)T_STEPS * G4)
        + (dir ? (size_t)(T_STEPS - 1) * G4 : 0) + row;
    const float* q1 = q0 + (size_t)T_STEPS * G4;   // seq bbase+1
    float pc0 = __ldg(q0),          pc1 = __ldg(q1);
    float p10 = __ldg(q0 + pstep),  p11 = __ldg(q1 + pstep);
    q0 += 2 * pstep;  q1 += 2 * pstep;

    const bool owner = (g < 2) && jvalid;
    float c = 0.0f;
    const size_t oseq = (size_t)T_STEPS * 2 * H;
    float* op = out + (size_t)(bbase + (g < 2 ? g : 0)) * oseq + dir * H + jj;

    __syncthreads();

    #pragma unroll 2
    for (int t = 0; t < T_STEPS; t++) {
        const int cur = t & 1;
        const int nxt = cur ^ 1;

        // prefetch pre for t+2
        const float p20 = __ldg(q0);  q0 += pstep;
        const float p21 = __ldg(q1);  q1 += pstep;

        // ---- this gate row's W_hh·h for both seqs (interleaved ILP) ----
        const float4* h40 = reinterpret_cast<const float4*>(sh[cur][0]);
        const float4* h41 = reinterpret_cast<const float4*>(sh[cur][1]);
        float2 A0 = make_float2(0.f, 0.f);
        float2 A1 = make_float2(0.f, 0.f);
        #pragma unroll
        for (int k = 0; k < 10; k++) {
            const float4 h0 = h40[k];
            const float4 h1 = h41[k];
            A0 = ffma2(whh2[2 * k],     make_float2(h0.x, h0.y), A0);
            A0 = ffma2(whh2[2 * k + 1], make_float2(h0.z, h0.w), A0);
            A1 = ffma2(whh2[2 * k],     make_float2(h1.x, h1.y), A1);
            A1 = ffma2(whh2[2 * k + 1], make_float2(h1.z, h1.w), A1);
        }
        const float pa = pc0 + (A0.x + A0.y);
        const float pb = pc1 + (A1.x + A1.y);
        // sigmoid(p)=1/(1+e^-p); tanh(p)=(e^{2p}-1)/(e^{2p}+1)
        const float ea = __expf(pa * mconst);
        const float a0 = __fdividef(fmaf(ea, nA, nB), ea + 1.0f);
        const float eb = __expf(pb * mconst);
        const float a1 = __fdividef(fmaf(eb, nA, nB), eb + 1.0f);
        const float a2 = 0.0f, a3 = 0.0f;   // seqs 2,3 absent (folds)

        // ---- 4x4 lane transpose: lane g gets gates [i,f,g,o] of seq g ----
        const unsigned M = 0xffffffffu;
        const bool o1 = (g & 1);
        const float rA = __shfl_xor_sync(M, o1 ? a0 : a1, 1);
        const float rB = __shfl_xor_sync(M, o1 ? a2 : a3, 1);
        const float n10 = o1 ? rA : a0;
        const float n11 = o1 ? a1 : rA;
        const float n12 = o1 ? rB : a2;
        const float n13 = o1 ? a3 : rB;
        const bool o2 = (g & 2);
        const float rC = __shfl_xor_sync(M, o2 ? n10 : n12, 2);
        const float rD = __shfl_xor_sync(M, o2 ? n11 : n13, 2);
        const float gi = o2 ? rC  : n10;
        const float gf = o2 ? rD  : n11;
        const float gg = o2 ? n12 : rC;
        const float go = o2 ? n13 : rD;

        // ---- cell update for owned (seq=g, j) ----
        c = gf * c + gi * gg;
        const float e2 = __expf(c + c);
        const float th = 1.0f - 2.0f * __fdividef(1.0f, e2 + 1.0f);  // tanh(c)
        const float h  = go * th;

        if (owner) {
            sh[nxt][g][jj] = h;
            *op = h;
        }
        op += 2 * H;

        pc0 = p10; p10 = p20;
        pc1 = p11; p11 = p21;

        __syncthreads();
    }
}

extern "C" void kernel_launch(void* const* d_in, const int* in_sizes, int n_in,
                              void* d_out, int out_size) {
    const float* x     = (const float*)d_in[0];
    const float* Wih_f = (const float*)d_in[1];
    const float* Whh_f = (const float*)d_in[2];
    const float* bih_f = (const float*)d_in[3];
    const float* bhh_f = (const float*)d_in[4];
    const float* Wih_b = (const float*)d_in[5];
    const float* Whh_b = (const float*)d_in[6];
    const float* bih_b = (const float*)d_in[7];
    const float* bhh_b = (const float*)d_in[8];
    float* out = (float*)d_out;

    pre_kernel<<<2 * B_TOT * NBLKT, THREADS>>>(x, Wih_f, bih_f, bhh_f,
                                               Wih_b, bih_b, bhh_b);
    lstm_rec_kernel<<<512, THREADS>>>(Whh_f, Whh_b, out);
}

// round 14
// speedup vs baseline: 1.1395x; 1.0594x over previous
#include <cuda_runtime.h>

// Bidirectional LSTM, H=39, B=512, T=2048, fp32 — two-phase.
// Phase 1 (pre_kernel): pre[d][b][t][row] = s_row * (W_ih[row,:]·x[b,t,:] + b_ih+b_hh),
//   s_row = 2 for tanh rows (78..116), 1 otherwise (folds the tanh input scale).
// Phase 2 (lstm_rec_kernel): WARP-PER-SEQUENCE, barrier-free recurrence.
//   1024 blocks x 32 threads; block (= warp) owns one (dir, batch) sequence.
//   Lane l holds W_hh rows {l+32s, s=0..4} in registers (g-rows prescaled x2).
//   h and gates exchanged via per-warp smem with __syncwarp only; zero
//   inter-warp coupling -> bubbles overlap across ~7 independent warps/SM.
//   R12 fix: pre-read offsets clamped for slots with row >= 156 (R11 read 4
//   rows past the stride, overrunning g_pre's tail at dir=1,b=511,t=2047).

#define H        39
#define G4       156
#define T_STEPS  2048
#define B_TOT    512
#define THREADS  160
#define PADW     40
#define TCH      64
#define TBLK     128
#define NBLKT    (T_STEPS / TBLK)   // 16

// 2 * 512 * 2048 * 156 floats = 1.31 GB scratch (bss)
__device__ float g_pre[2ULL * B_TOT * T_STEPS * G4];

union F2U { float2 f; unsigned long long u; };

__device__ __forceinline__ float2 ffma2(float2 a, float2 b, float2 c) {
    F2U A, B, C, D;
    A.f = a; B.f = b; C.f = c;
    asm("fma.rn.f32x2 %0, %1, %2, %3;" : "=l"(D.u) : "l"(A.u), "l"(B.u), "l"(C.u));
    return D.f;
}

// ---------------------------------------------------------------------------
// Phase 1. grid = 2*512*16 blocks x 160 thr. Subgroup tid/80 owns 64 tt of a
// 128-tt staged x tile; thread r (<78) owns rows r and r+78 (80 weight regs).
// ---------------------------------------------------------------------------
__global__ __launch_bounds__(THREADS) void pre_kernel(
    const float* __restrict__ x,
    const float* __restrict__ Wih_f, const float* __restrict__ bih_f,
    const float* __restrict__ bhh_f,
    const float* __restrict__ Wih_b, const float* __restrict__ bih_b,
    const float* __restrict__ bhh_b)
{
    __shared__ __align__(16) float sxt[TBLK][PADW];

    const int tid = threadIdx.x;
    const int bx  = blockIdx.x;
    const int tb  = bx & (NBLKT - 1);
    const int bb  = (bx >> 4) & (B_TOT - 1);
    const int d   = bx >> 13;

    const float* Wih = d ? Wih_b : Wih_f;
    const float* bih = d ? bih_b : bih_f;
    const float* bhh = d ? bhh_b : bhh_f;

    const float* xb = x + ((size_t)bb * T_STEPS + (size_t)tb * TBLK) * H;
    for (int idx = tid; idx < TBLK * H; idx += THREADS) {
        const int t = idx / H;
        const int k = idx - t * H;
        sxt[t][k] = xb[idx];
    }
    for (int t = tid; t < TBLK; t += THREADS) sxt[t][H] = 0.0f;

    const int sub = (tid >= 80) ? 1 : 0;
    const int r   = tid - 80 * sub;
    const bool valid = (r < 78);
    const int r0 = valid ? r : 77;
    const int r1 = r0 + 78;

    float2 w0[20], w1[20];
    #pragma unroll
    for (int k = 0; k < 20; k++) {
        const int i0 = 2 * k, i1 = i0 + 1;
        const float a0 = Wih[r0 * H + i0];
        const float a1 = (i1 < H) ? Wih[r0 * H + i1] : 0.0f;
        const float b0 = Wih[r1 * H + i0];
        const float b1 = (i1 < H) ? Wih[r1 * H + i1] : 0.0f;
        w0[k] = make_float2(a0, a1);
        w1[k] = make_float2(b0, b1);
    }
    const float bias0 = bih[r0] + bhh[r0];
    const float bias1 = bih[r1] + bhh[r1];
    // fold tanh input scale: g rows are 78..116 -> only possible in r1
    const float sc1 = (r1 < 117) ? 2.0f : 1.0f;

    __syncthreads();

    const float (*tile)[PADW] = &sxt[sub * TCH];
    float* po = g_pre + (((size_t)d * B_TOT + bb) * T_STEPS
                         + (size_t)tb * TBLK + (size_t)sub * TCH) * G4;

    #pragma unroll 2
    for (int tt = 0; tt < TCH; tt++) {
        const float4* x4 = reinterpret_cast<const float4*>(tile[tt]);
        float2 acc0 = make_float2(0.f, 0.f);
        float2 acc1 = make_float2(0.f, 0.f);
        #pragma unroll
        for (int k = 0; k < 10; k++) {
            const float4 xv = x4[k];
            const float2 lo = make_float2(xv.x, xv.y);
            const float2 hi = make_float2(xv.z, xv.w);
            acc0 = ffma2(w0[2 * k],     lo, acc0);
            acc0 = ffma2(w0[2 * k + 1], hi, acc0);
            acc1 = ffma2(w1[2 * k],     lo, acc1);
            acc1 = ffma2(w1[2 * k + 1], hi, acc1);
        }
        if (valid) {
            po[(size_t)tt * G4 + r0] = bias0 + acc0.x + acc0.y;
            po[(size_t)tt * G4 + r1] = sc1 * (bias1 + acc1.x + acc1.y);
        }
    }
}

// ---------------------------------------------------------------------------
// Phase 2: warp-per-sequence recurrence. 1024 blocks x 32 threads.
// ---------------------------------------------------------------------------
__global__ __launch_bounds__(32) void lstm_rec_kernel(
    const float* __restrict__ Whh_f, const float* __restrict__ Whh_b,
    float* __restrict__ out)
{
    __shared__ __align__(16) float sh_h[PADW];   // h (40, pad elem 39 = 0)
    __shared__ float sg[G4 + 4];                 // activated gates by row

    const int l  = threadIdx.x;
    const int bx = blockIdx.x;
    const int dir = bx >> 9;
    const int bb  = bx & (B_TOT - 1);

    const float* Whh = dir ? Whh_b : Whh_f;

    // ---- weights: slot s -> row r = l + 32s; g rows (78..116) prescaled x2 ----
    float2 w[5][20];
    float ka[5];
    int   off[5];                    // clamped pre-read offset per slot
    #pragma unroll
    for (int s = 0; s < 5; s++) {
        const int r = l + 32 * s;
        const bool ok  = (r < G4);
        off[s] = ok ? 32 * s : 0;    // invalid slot re-reads row l (discarded)
        const int  rc  = ok ? r : 0;
        const bool isg = (rc >= 2 * H) && (rc < 3 * H);
        const float ws = ok ? (isg ? 2.0f : 1.0f) : 0.0f;
        ka[s] = isg ? 2.0f : 1.0f;
        #pragma unroll
        for (int k = 0; k < 20; k++) {
            const int i0 = 2 * k, i1 = i0 + 1;
            const float a = Whh[rc * H + i0] * ws;
            const float b = (i1 < H) ? Whh[rc * H + i1] * ws : 0.0f;
            w[s][k] = make_float2(a, b);
        }
    }

    // ---- init smem h = 0 ----
    sh_h[l] = 0.0f;
    if (l < 8) sh_h[32 + l] = 0.0f;

    // ---- pre pointer + 1-step prefetch ----
    // Over-read at t == T_STEPS (dir=0) / t == -1 (dir=1) stays inside g_pre:
    // max row offset is now 155, so the worst index is exactly the last
    // element (dir=1, b=511, t=2047) or one timestep into the other half.
    const long pstep = dir ? -(long)G4 : (long)G4;
    const float* q = g_pre
        + ((size_t)dir * B_TOT + bb) * ((size_t)T_STEPS * G4)
        + (dir ? (size_t)(T_STEPS - 1) * G4 : 0) + l;
    float pc[5];
    #pragma unroll
    for (int s = 0; s < 5; s++) pc[s] = __ldg(q + off[s]);
    q += pstep;

    float* op = out + (size_t)bb * (T_STEPS * 2 * H) + dir * H + l;

    float c0 = 0.0f, c1 = 0.0f;
    __syncwarp();

    #pragma unroll 1
    for (int t = 0; t < T_STEPS; t++) {
        // prefetch pre for t+1
        float pn[5];
        #pragma unroll
        for (int s = 0; s < 5; s++) pn[s] = __ldg(q + off[s]);
        q += pstep;

        // ---- matvec: 5 rows/lane, h broadcast via uniform LDS.128 ----
        float2 acc[5];
        #pragma unroll
        for (int s = 0; s < 5; s++) acc[s] = make_float2(0.f, 0.f);
        const float4* h4 = reinterpret_cast<const float4*>(sh_h);
        #pragma unroll
        for (int k = 0; k < 10; k++) {
            const float4 hv = h4[k];
            const float2 lo = make_float2(hv.x, hv.y);
            const float2 hi = make_float2(hv.z, hv.w);
            #pragma unroll
            for (int s = 0; s < 5; s++) {
                acc[s] = ffma2(w[s][2 * k],     lo, acc[s]);
                acc[s] = ffma2(w[s][2 * k + 1], hi, acc[s]);
            }
        }

        // ---- unified activation: y = fma(ka, 1/(1+e^-p) - 1, 1) ----
        #pragma unroll
        for (int s = 0; s < 5; s++) {
            const float p = pc[s] + acc[s].x + acc[s].y;
            const float e = __expf(-p);
            const float u = __fdividef(1.0f, 1.0f + e);
            const float y = fmaf(ka[s], u - 1.0f, 1.0f);
            const int r = l + 32 * s;
            if (r < G4) sg[r] = y;
        }
        __syncwarp();

        // ---- cell update: lane l owns cell l; lanes 0..6 also cell 32+l ----
        {
            const float gi = sg[l];
            const float gf = sg[H + l];
            const float gg = sg[2 * H + l];
            const float go = sg[3 * H + l];
            c0 = fmaf(gf, c0, gi * gg);
            const float e2 = __expf(c0 + c0);
            const float th = 1.0f - 2.0f * __fdividef(1.0f, e2 + 1.0f);
            const float h0 = go * th;
            sh_h[l] = h0;
            op[0] = h0;
        }
        if (l < 7) {
            const int j = 32 + l;
            const float gi = sg[j];
            const float gf = sg[H + j];
            const float gg = sg[2 * H + j];
            const float go = sg[3 * H + j];
            c1 = fmaf(gf, c1, gi * gg);
            const float e2 = __expf(c1 + c1);
            const float th = 1.0f - 2.0f * __fdividef(1.0f, e2 + 1.0f);
            const float h1 = go * th;
            sh_h[j] = h1;
            op[32] = h1;
        }
        __syncwarp();

        #pragma unroll
        for (int s = 0; s < 5; s++) pc[s] = pn[s];
        op += 2 * H;
    }
}

extern "C" void kernel_launch(void* const* d_in, const int* in_sizes, int n_in,
                              void* d_out, int out_size) {
    const float* x     = (const float*)d_in[0];
    const float* Wih_f = (const float*)d_in[1];
    const float* Whh_f = (const float*)d_in[2];
    const float* bih_f = (const float*)d_in[3];
    const float* bhh_f = (const float*)d_in[4];
    const float* Wih_b = (const float*)d_in[5];
    const float* Whh_b = (const float*)d_in[6];
    const float* bih_b = (const float*)d_in[7];
    const float* bhh_b = (const float*)d_in[8];
    float* out = (float*)d_out;

    pre_kernel<<<2 * B_TOT * NBLKT, THREADS>>>(x, Wih_f, bih_f, bhh_f,
                                               Wih_b, bih_b, bhh_b);
    lstm_rec_kernel<<<2 * B_TOT, 32>>>(Whh_f, Whh_b, out);
}